// round 4
// baseline (speedup 1.0000x reference)
#include <cuda_runtime.h>
#include <math.h>

#define BB 16
#define SS 2048
#define DD 256
#define HM 256            // fast-memory hidden dim (H in reference = 256!)
#define PP 8
#define CHN 16
#define CC 128
#define LL 264            // PP + 2*CC
#define NH 8
#define HD 32
#define NSEG 16
#define PER (DD*HM + HM + HM*DD + DD)
#define LD_INV (1.0f/((float)LL*(float)DD))

// ---------------- persistent scratch (device globals; no allocation) -------
__device__ __align__(16) float g_fastW1[BB*DD*HM];
__device__ __align__(16) float g_fastb1[BB*HM];
__device__ __align__(16) float g_fastW2[BB*HM*DD];
__device__ __align__(16) float g_fastb2[BB*DD];
__device__ __align__(16) float g_momW1[BB*DD*HM];
__device__ __align__(16) float g_momb1[BB*HM];
__device__ __align__(16) float g_momW2[BB*HM*DD];
__device__ __align__(16) float g_momb2[BB*DD];
__device__ __align__(16) float g_gW1[BB*DD*HM];
__device__ __align__(16) float g_gb1[BB*HM];
__device__ __align__(16) float g_gW2[BB*HM*DD];
__device__ __align__(16) float g_gb2[BB*DD];
__device__ __align__(16) float g_attn[BB*LL*DD];
__device__ __align__(16) float g_q[BB*CC*DD];
__device__ __align__(16) float g_h1[BB*CC*HM];
__device__ __align__(16) float g_fo[BB*CC*DD];
__device__ __align__(16) float g_qkv[BB*LL*3*DD];
__device__ __align__(16) float g_ao[BB*LL*DD];
__device__ __align__(16) float g_y[BB*LL*DD];
__device__ __align__(16) float g_k[BB*LL*DD];
__device__ __align__(16) float g_v[BB*LL*DD];
__device__ __align__(16) float g_z[BB*LL*HM];
__device__ __align__(16) float g_s[BB*LL*HM];
__device__ __align__(16) float g_ds[BB*LL*HM];
__device__ __align__(16) float g_dz[BB*LL*HM];
__device__ __align__(16) float g_pred[BB*LL*DD];
__device__ __align__(16) float g_e[BB*LL*DD];
__device__ float g_coef[BB*3];

// ---------------- init fast weights / momentum each call -------------------
__global__ void k_init(const float* __restrict__ mW1, const float* __restrict__ mb1,
                       const float* __restrict__ mW2, const float* __restrict__ mb2) {
    long i = (long)blockIdx.x * blockDim.x + threadIdx.x;
    if (i < (long)BB*DD*HM) {
        g_fastW1[i] = mW1[i % (DD*HM)]; g_momW1[i] = 0.f;
        g_fastW2[i] = mW2[i % (HM*DD)]; g_momW2[i] = 0.f;
    }
    if (i < BB*HM) { g_fastb1[i] = mb1[i % HM]; g_momb1[i] = 0.f; }
    if (i < BB*DD) { g_fastb2[i] = mb2[i % DD]; g_momb2[i] = 0.f; }
}

// ---------------- pack attn_in = [persistent | (h later) | seg] ------------
__global__ void k_pack(const float* __restrict__ x, const float* __restrict__ pers, int s0) {
    int i = blockIdx.x * blockDim.x + threadIdx.x;
    if (i >= BB*LL*DD) return;
    int d = i % DD;
    int t = (i / DD) % LL;
    int b = i / (LL*DD);
    if (t < PP)            g_attn[i] = pers[t*DD + d];
    else if (t >= PP + CC) g_attn[i] = x[(size_t)b*SS*DD + (size_t)(s0 + t - (PP+CC))*DD + d];
}

// ---------------- shared-weight GEMM:  C = A @ B (or A @ B^T) [+ bias] -----
// rows batched: row r -> A + (r/rowsPerBatch)*strideA + (r%rowsPerBatch)*K
// 64 | rowsPerBatch required. TB: B is N x K (C = A @ B^T), else K x N.
template<bool TB, bool BIAS>
__global__ void k_gemm(const float* __restrict__ A, const float* __restrict__ Bw,
                       const float* __restrict__ bias, float* __restrict__ C,
                       int N, int K, int rowsPerBatch, long strideA, long strideC) {
    __shared__ float As[16][68];
    __shared__ float Bs[16][68];
    int tid = threadIdx.x;
    int n0 = blockIdx.x * 64;
    int m0 = blockIdx.y * 64;
    int bb = m0 / rowsPerBatch;
    int local = m0 - bb*rowsPerBatch;
    const float* Abase = A + (long)bb*strideA + (long)local*K;
    float* Cbase = C + (long)bb*strideC + (long)local*N;
    int tx = tid & 15, ty = tid >> 4;
    float acc[4][4] = {};
    int ar = tid >> 2, ac = (tid & 3) * 4;
    for (int k0 = 0; k0 < K; k0 += 16) {
        float4 av = *(const float4*)(Abase + (long)ar*K + k0 + ac);
        As[ac+0][ar] = av.x; As[ac+1][ar] = av.y; As[ac+2][ar] = av.z; As[ac+3][ar] = av.w;
        if (TB) {
            int nr = tid >> 2, kc = (tid & 3) * 4;
            float4 bv = *(const float4*)(Bw + (long)(n0+nr)*K + k0 + kc);
            Bs[kc+0][nr] = bv.x; Bs[kc+1][nr] = bv.y; Bs[kc+2][nr] = bv.z; Bs[kc+3][nr] = bv.w;
        } else {
            int br = tid >> 4, bc = (tid & 15) * 4;
            float4 bv = *(const float4*)(Bw + (long)(k0+br)*N + n0 + bc);
            Bs[br][bc+0] = bv.x; Bs[br][bc+1] = bv.y; Bs[br][bc+2] = bv.z; Bs[br][bc+3] = bv.w;
        }
        __syncthreads();
        #pragma unroll
        for (int kk = 0; kk < 16; kk++) {
            float a[4], bv[4];
            #pragma unroll
            for (int i = 0; i < 4; i++) a[i] = As[kk][ty*4+i];
            #pragma unroll
            for (int j = 0; j < 4; j++) bv[j] = Bs[kk][tx*4+j];
            #pragma unroll
            for (int i = 0; i < 4; i++)
                #pragma unroll
                for (int j = 0; j < 4; j++) acc[i][j] += a[i] * bv[j];
        }
        __syncthreads();
    }
    #pragma unroll
    for (int i = 0; i < 4; i++) {
        #pragma unroll
        for (int j = 0; j < 4; j++) {
            int col = n0 + tx*4 + j;
            float v = acc[i][j];
            if (BIAS) v += bias[col];
            Cbase[(long)(ty*4+i)*N + col] = v;
        }
    }
}

// ---------------- per-batch-weight GEMM (blockIdx.z = batch), bounded M ----
// ACT: 0 none, 1 silu
template<bool TB, int ACT, bool BIAS>
__global__ void k_gemmB(const float* __restrict__ A, const float* __restrict__ Bw,
                        const float* __restrict__ bias, float* __restrict__ C,
                        int M, int N, int K,
                        long strideA, long strideB, long strideC, int biasStride) {
    __shared__ float As[16][68];
    __shared__ float Bs[16][68];
    int b = blockIdx.z;
    A  += (long)b * strideA;
    Bw += (long)b * strideB;
    C  += (long)b * strideC;
    if (BIAS) bias += (long)b * biasStride;
    int tid = threadIdx.x;
    int n0 = blockIdx.x * 64;
    int m0 = blockIdx.y * 64;
    int tx = tid & 15, ty = tid >> 4;
    float acc[4][4] = {};
    int ar = tid >> 2, ac = (tid & 3) * 4;
    int arow = m0 + ar; if (arow >= M) arow = 0;   // clamp (stores are guarded)
    for (int k0 = 0; k0 < K; k0 += 16) {
        float4 av = *(const float4*)(A + (long)arow*K + k0 + ac);
        As[ac+0][ar] = av.x; As[ac+1][ar] = av.y; As[ac+2][ar] = av.z; As[ac+3][ar] = av.w;
        if (TB) {
            int nr = tid >> 2, kc = (tid & 3) * 4;
            float4 bv = *(const float4*)(Bw + (long)(n0+nr)*K + k0 + kc);
            Bs[kc+0][nr] = bv.x; Bs[kc+1][nr] = bv.y; Bs[kc+2][nr] = bv.z; Bs[kc+3][nr] = bv.w;
        } else {
            int br = tid >> 4, bc = (tid & 15) * 4;
            float4 bv = *(const float4*)(Bw + (long)(k0+br)*N + n0 + bc);
            Bs[br][bc+0] = bv.x; Bs[br][bc+1] = bv.y; Bs[br][bc+2] = bv.z; Bs[br][bc+3] = bv.w;
        }
        __syncthreads();
        #pragma unroll
        for (int kk = 0; kk < 16; kk++) {
            float a[4], bv[4];
            #pragma unroll
            for (int i = 0; i < 4; i++) a[i] = As[kk][ty*4+i];
            #pragma unroll
            for (int j = 0; j < 4; j++) bv[j] = Bs[kk][tx*4+j];
            #pragma unroll
            for (int i = 0; i < 4; i++)
                #pragma unroll
                for (int j = 0; j < 4; j++) acc[i][j] += a[i] * bv[j];
        }
        __syncthreads();
    }
    #pragma unroll
    for (int i = 0; i < 4; i++) {
        int row = m0 + ty*4 + i;
        if (row < M) {
            #pragma unroll
            for (int j = 0; j < 4; j++) {
                int col = n0 + tx*4 + j;
                float v = acc[i][j];
                if (BIAS) v += bias[col];
                if (ACT == 1) v = v / (1.f + expf(-v));
                C[(long)row*N + col] = v;
            }
        }
    }
}

// ---------------- per-batch reduction GEMM: C[m,n] = sum_t A[t,m]*B[t,n] ---
// T must be a multiple of 8 (264 = 33*8). M, N multiples of 64.
__global__ void k_gemmTA(const float* __restrict__ A, const float* __restrict__ B,
                         float* __restrict__ C, int T, int M, int N,
                         long strideA, long strideB, long strideC) {
    __shared__ float As[8][68];
    __shared__ float Bs[8][68];
    int b = blockIdx.z;
    A += (long)b * strideA;
    B += (long)b * strideB;
    C += (long)b * strideC;
    int tid = threadIdx.x;
    int n0 = blockIdx.x * 64;
    int m0 = blockIdx.y * 64;
    int tx = tid & 15, ty = tid >> 4;
    float acc[4][4] = {};
    int lr = tid >> 5;           // 0..7  (t within chunk)
    int lc = (tid & 31) * 2;     // 0..62 (col pair)
    for (int t0 = 0; t0 < T; t0 += 8) {
        int ta = t0 + lr;
        float2 av = *(const float2*)(A + (long)ta*M + m0 + lc);
        As[lr][lc] = av.x; As[lr][lc+1] = av.y;
        float2 bv = *(const float2*)(B + (long)ta*N + n0 + lc);
        Bs[lr][lc] = bv.x; Bs[lr][lc+1] = bv.y;
        __syncthreads();
        #pragma unroll
        for (int kk = 0; kk < 8; kk++) {
            float a[4], bv2[4];
            #pragma unroll
            for (int i = 0; i < 4; i++) a[i] = As[kk][ty*4+i];
            #pragma unroll
            for (int j = 0; j < 4; j++) bv2[j] = Bs[kk][tx*4+j];
            #pragma unroll
            for (int i = 0; i < 4; i++)
                #pragma unroll
                for (int j = 0; j < 4; j++) acc[i][j] += a[i] * bv2[j];
        }
        __syncthreads();
    }
    #pragma unroll
    for (int i = 0; i < 4; i++)
        #pragma unroll
        for (int j = 0; j < 4; j++)
            C[(long)(m0+ty*4+i)*N + n0 + tx*4 + j] = acc[i][j];
}

// ---------------- attention: one warp per (b, head, query-row) -------------
__global__ void k_attn() {
    int gw = (blockIdx.x * blockDim.x + threadIdx.x) >> 5;
    int lane = threadIdx.x & 31;
    if (gw >= BB*NH*LL) return;
    int r = gw % LL;
    int hh = (gw / LL) % NH;
    int b  = gw / (LL*NH);
    const float* base = g_qkv + (long)b*LL*3*DD;
    const float* qp = base + (long)r*3*DD + hh*HD;
    float qv = qp[lane] * 0.17677669529663687f;   // 1/sqrt(32)
    const float* Kp = base + DD   + hh*HD;
    const float* Vp = base + 2*DD + hh*HD;
    float m = -1e30f, l = 0.f, o = 0.f;
    int nch = r/32 + 1;
    for (int c = 0; c < nch; c++) {
        int j = c*32 + lane;
        int jc = j <= r ? j : r;
        const float* kr = Kp + (long)jc*3*DD;
        float sc = 0.f;
        #pragma unroll
        for (int d = 0; d < 32; d++) {
            float qd = __shfl_sync(0xffffffffu, qv, d);
            sc += qd * kr[d];
        }
        if (j > r) sc = -1e30f;
        float cm = sc;
        #pragma unroll
        for (int s = 16; s; s >>= 1) cm = fmaxf(cm, __shfl_xor_sync(0xffffffffu, cm, s));
        float mn = fmaxf(m, cm);
        float p = (j <= r) ? expf(sc - mn) : 0.f;
        float ps = p;
        #pragma unroll
        for (int s = 16; s; s >>= 1) ps += __shfl_xor_sync(0xffffffffu, ps, s);
        float corr = expf(m - mn);
        l = l*corr + ps;
        o = o*corr;
        m = mn;
        int jmax = min(32, r - c*32 + 1);
        const float* vr = Vp + (long)(c*32)*3*DD;
        for (int jj = 0; jj < jmax; jj++) {
            float pj = __shfl_sync(0xffffffffu, p, jj);
            o += pj * vr[(long)jj*3*DD + lane];
        }
    }
    g_ao[((long)b*LL + r)*DD + hh*HD + lane] = o / l;
}

// ---------------- elementwise pieces ---------------------------------------
__global__ void k_silu() {
    int i = blockIdx.x * blockDim.x + threadIdx.x;
    if (i >= BB*LL*HM) return;
    float z = g_z[i];
    g_s[i] = z / (1.f + expf(-z));
}
__global__ void k_err() {
    int i = blockIdx.x * blockDim.x + threadIdx.x;
    if (i >= BB*LL*DD) return;
    g_e[i] = (g_pred[i] - g_v[i]) * LD_INV;
}
__global__ void k_dz() {
    int i = blockIdx.x * blockDim.x + threadIdx.x;
    if (i >= BB*LL*HM) return;
    float z = g_z[i];
    float sig = 1.f / (1.f + expf(-z));
    g_dz[i] = g_ds[i] * sig * (1.f + z * (1.f - sig));
}

// ---------------- bias grads: gb2 = sum_t e, gb1 = sum_t dz ---------------
__global__ void k_gbias() {
    int b = blockIdx.x, tid = threadIdx.x;
    if (blockIdx.y == 0) {
        const float* p = g_e + (long)b*LL*DD + tid;
        float s = 0.f;
        for (int t = 0; t < LL; t++) s += p[(long)t*DD];
        g_gb2[b*DD + tid] = s;
    } else {
        const float* p = g_dz + (long)b*LL*HM + tid;
        float s = 0.f;
        for (int t = 0; t < LL; t++) s += p[(long)t*HM];
        g_gb1[b*HM + tid] = s;
    }
}

// ---------------- gate coefficients ----------------------------------------
__global__ void k_coef(const float* __restrict__ cW1, const float* __restrict__ cb1,
                       const float* __restrict__ cW2, const float* __restrict__ cb2) {
    int b = blockIdx.x, tid = threadIdx.x;
    __shared__ float ybar[DD];
    __shared__ float ch[CHN];
    float sum = 0.f;
    const float* yp = g_y + (long)b*LL*DD + tid;
    for (int t = 0; t < LL; t++) sum += yp[(long)t*DD];
    ybar[tid] = sum / (float)LL;
    __syncthreads();
    if (tid < CHN) {
        float a = cb1[tid];
        for (int d = 0; d < DD; d++) a += ybar[d] * cW1[d*CHN + tid];
        ch[tid] = a / (1.f + expf(-a));
    }
    __syncthreads();
    if (tid < 3) {
        float a = cb2[tid];
        for (int j = 0; j < CHN; j++) a += ch[j] * cW2[j*3 + tid];
        g_coef[b*3 + tid] = 1.f / (1.f + expf(-a));
    }
}

// ---------------- momentum + decay update ----------------------------------
__global__ void k_update() {
    long i = (long)blockIdx.x * blockDim.x + threadIdx.x;
    if (i >= (long)BB*PER) return;
    int b = (int)(i / PER), off = (int)(i % PER);
    float alpha = g_coef[b*3+0], eta = g_coef[b*3+1], theta = g_coef[b*3+2];
    float *fp, *mp, *gp;
    long idx;
    if (off < DD*HM)                  { fp = g_fastW1; mp = g_momW1; gp = g_gW1; idx = (long)b*DD*HM + off; }
    else if (off < DD*HM + HM)        { int o = off - DD*HM; fp = g_fastb1; mp = g_momb1; gp = g_gb1; idx = b*HM + o; }
    else if (off < DD*HM + HM + HM*DD){ int o = off - DD*HM - HM; fp = g_fastW2; mp = g_momW2; gp = g_gW2; idx = (long)b*HM*DD + o; }
    else                              { int o = off - DD*HM - HM - HM*DD; fp = g_fastb2; mp = g_momb2; gp = g_gb2; idx = b*DD + o; }
    float m = eta * mp[idx] - theta * gp[idx];
    mp[idx] = m;
    fp[idx] = (1.f - alpha) * fp[idx] + m;
}

// ---------------- final gate: out = y_last * mem_out -----------------------
__global__ void k_gate(float* __restrict__ out, int s0) {
    int i = blockIdx.x * blockDim.x + threadIdx.x;
    if (i >= BB*CC*DD) return;
    int d = i % DD;
    int t = (i / DD) % CC;
    int b = i / (CC*DD);
    float yv = g_y[((long)b*LL + PP + CC + t)*DD + d];
    out[(size_t)b*SS*DD + (size_t)(s0 + t)*DD + d] = yv * g_fo[(long)(b*CC + t)*DD + d];
}

// ---------------------------------------------------------------------------
extern "C" void kernel_launch(void* const* d_in, const int* in_sizes, int n_in,
                              void* d_out, int out_size) {
    const float* x     = (const float*)d_in[0];
    const float* pers  = (const float*)d_in[1];
    const float* W_Q   = (const float*)d_in[2];
    const float* in_w  = (const float*)d_in[3];
    const float* in_b  = (const float*)d_in[4];
    const float* out_w = (const float*)d_in[5];
    const float* out_b = (const float*)d_in[6];
    const float* mW1   = (const float*)d_in[7];
    const float* mb1   = (const float*)d_in[8];
    const float* mW2   = (const float*)d_in[9];
    const float* mb2   = (const float*)d_in[10];
    const float* W_K   = (const float*)d_in[11];
    const float* W_V   = (const float*)d_in[12];
    const float* cW1   = (const float*)d_in[13];
    const float* cb1   = (const float*)d_in[14];
    const float* cW2   = (const float*)d_in[15];
    const float* cb2   = (const float*)d_in[16];
    float* out = (float*)d_out;

    float* fW1 = nullptr; float* fb1 = nullptr; float* fW2 = nullptr; float* fb2 = nullptr;
    cudaGetSymbolAddress((void**)&fW1, g_fastW1);
    cudaGetSymbolAddress((void**)&fb1, g_fastb1);
    cudaGetSymbolAddress((void**)&fW2, g_fastW2);
    cudaGetSymbolAddress((void**)&fb2, g_fastb2);
    float* pQ = nullptr; float* pH1 = nullptr; float* pAttn = nullptr; float* pK = nullptr;
    float* pZ = nullptr; float* pS = nullptr; float* pPred = nullptr; float* pE = nullptr;
    float* pDs = nullptr; float* pDz = nullptr; float* pGW1 = nullptr; float* pGW2 = nullptr;
    float* pQkv = nullptr; float* pAo = nullptr; float* pY = nullptr; float* pV = nullptr; float* pFo = nullptr;
    cudaGetSymbolAddress((void**)&pQ, g_q);
    cudaGetSymbolAddress((void**)&pH1, g_h1);
    cudaGetSymbolAddress((void**)&pAttn, g_attn);
    cudaGetSymbolAddress((void**)&pK, g_k);
    cudaGetSymbolAddress((void**)&pZ, g_z);
    cudaGetSymbolAddress((void**)&pS, g_s);
    cudaGetSymbolAddress((void**)&pPred, g_pred);
    cudaGetSymbolAddress((void**)&pE, g_e);
    cudaGetSymbolAddress((void**)&pDs, g_ds);
    cudaGetSymbolAddress((void**)&pDz, g_dz);
    cudaGetSymbolAddress((void**)&pGW1, g_gW1);
    cudaGetSymbolAddress((void**)&pGW2, g_gW2);
    cudaGetSymbolAddress((void**)&pQkv, g_qkv);
    cudaGetSymbolAddress((void**)&pAo, g_ao);
    cudaGetSymbolAddress((void**)&pY, g_y);
    cudaGetSymbolAddress((void**)&pV, g_v);
    cudaGetSymbolAddress((void**)&pFo, g_fo);

    k_init<<<((long)BB*DD*HM + 255)/256, 256>>>(mW1, mb1, mW2, mb2);

    for (int s = 0; s < NSEG; s++) {
        int s0 = s * CC;
        k_pack<<<(BB*LL*DD + 255)/256, 256>>>(x, pers, s0);

        // q = seg @ W_Q
        k_gemm<false,false><<<dim3(DD/64, (BB*CC)/64), 256>>>(
            x + (long)s0*DD, W_Q, nullptr, pQ, DD, DD, CC, (long)SS*DD, (long)CC*DD);

        // h1 = silu(q @ fastW1 + fastb1)    [per-batch weights]
        k_gemmB<false,1,true><<<dim3(HM/64, CC/64, BB), 256>>>(
            pQ, fW1, fb1, pH1, CC, HM, DD, (long)CC*DD, (long)DD*HM, (long)CC*HM, HM);
        // h = h1 @ fastW2 + fastb2 -> attn_in rows [PP, PP+CC)
        k_gemmB<false,0,true><<<dim3(DD/64, CC/64, BB), 256>>>(
            pH1, fW2, fb2, pAttn + PP*DD, CC, DD, HM, (long)CC*HM, (long)HM*DD, (long)LL*DD, DD);

        // qkv = attn_in @ in_proj_w^T + in_proj_b
        k_gemm<true,true><<<dim3((3*DD)/64, (BB*LL)/64), 256>>>(
            pAttn, in_w, in_b, pQkv, 3*DD, DD, BB*LL, 0L, 0L);
        k_attn<<<(BB*NH*LL*32)/128, 128>>>();
        // y = ao @ out_proj_w^T + out_proj_b
        k_gemm<true,true><<<dim3(DD/64, (BB*LL)/64), 256>>>(
            pAo, out_w, out_b, pY, DD, DD, BB*LL, 0L, 0L);

        // k = y @ W_K ; v = y @ W_V
        k_gemm<false,false><<<dim3(DD/64, (BB*LL)/64), 256>>>(
            pY, W_K, nullptr, pK, DD, DD, BB*LL, 0L, 0L);
        k_gemm<false,false><<<dim3(DD/64, (BB*LL)/64), 256>>>(
            pY, W_V, nullptr, pV, DD, DD, BB*LL, 0L, 0L);

        // ---- gradient of 0.5*sum_b mean_{t,d}(pred - v)^2 ----
        // z = k @ W1 + b1
        k_gemmB<false,0,true><<<dim3(HM/64, (LL+63)/64, BB), 256>>>(
            pK, fW1, fb1, pZ, LL, HM, DD, (long)LL*DD, (long)DD*HM, (long)LL*HM, HM);
        k_silu<<<(BB*LL*HM + 255)/256, 256>>>();
        // pred = s @ W2 + b2
        k_gemmB<false,0,true><<<dim3(DD/64, (LL+63)/64, BB), 256>>>(
            pS, fW2, fb2, pPred, LL, DD, HM, (long)LL*HM, (long)HM*DD, (long)LL*DD, DD);
        k_err<<<(BB*LL*DD + 255)/256, 256>>>();
        // ds = e @ W2^T
        k_gemmB<true,0,false><<<dim3(HM/64, (LL+63)/64, BB), 256>>>(
            pE, fW2, nullptr, pDs, LL, HM, DD, (long)LL*DD, (long)HM*DD, (long)LL*HM, 0);
        k_dz<<<(BB*LL*HM + 255)/256, 256>>>();
        // gW2[h,d] = sum_t s[t,h]*e[t,d]
        k_gemmTA<<<dim3(DD/64, HM/64, BB), 256>>>(
            pS, pE, pGW2, LL, HM, DD, (long)LL*HM, (long)LL*DD, (long)HM*DD);
        // gW1[d,h] = sum_t k[t,d]*dz[t,h]
        k_gemmTA<<<dim3(HM/64, DD/64, BB), 256>>>(
            pK, pDz, pGW1, LL, DD, HM, (long)LL*DD, (long)LL*HM, (long)DD*HM);
        k_gbias<<<dim3(BB, 2), 256>>>();

        k_coef<<<BB, 256>>>(cW1, cb1, cW2, cb2);
        k_update<<<((long)BB*PER + 255)/256, 256>>>();

        // final: mem_out on last CC tokens of y with UPDATED weights, gate
        k_gemmB<false,1,true><<<dim3(HM/64, CC/64, BB), 256>>>(
            pY + (long)(PP+CC)*DD, fW1, fb1, pH1, CC, HM, DD, (long)LL*DD, (long)DD*HM, (long)CC*HM, HM);
        k_gemmB<false,0,true><<<dim3(DD/64, CC/64, BB), 256>>>(
            pH1, fW2, fb2, pFo, CC, DD, HM, (long)CC*HM, (long)HM*DD, (long)CC*DD, DD);
        k_gate<<<(BB*CC*DD + 255)/256, 256>>>(out, s0);
    }
}

// round 7
// speedup vs baseline: 3.9228x; 3.9228x over previous
#include <cuda_runtime.h>
#include <math.h>

#define BB 16
#define SS 2048
#define DD 256
#define HM 256
#define PP 8
#define CHN 16
#define CC 128
#define LL 264            // PP + 2*CC
#define NH 8
#define HD 32
#define NSEG 16
#define PER (DD*HM + HM + HM*DD + DD)
#define LD_INV (1.0f/((float)LL*(float)DD))

// ---------------- persistent scratch (device globals; no allocation) -------
__device__ __align__(16) float g_fastW1[BB*DD*HM];
__device__ __align__(16) float g_fastb1[BB*HM];
__device__ __align__(16) float g_fastW2[BB*HM*DD];
__device__ __align__(16) float g_fastb2[BB*DD];
__device__ __align__(16) float g_momW1[BB*DD*HM];
__device__ __align__(16) float g_momb1[BB*HM];
__device__ __align__(16) float g_momW2[BB*HM*DD];
__device__ __align__(16) float g_momb2[BB*DD];
__device__ __align__(16) float g_gW1[BB*DD*HM];
__device__ __align__(16) float g_gb1[BB*HM];
__device__ __align__(16) float g_gW2[BB*HM*DD];
__device__ __align__(16) float g_gb2[BB*DD];
__device__ __align__(16) float g_qall[BB*SS*DD];
__device__ __align__(16) float g_Wkv[DD*2*DD];
__device__ __align__(16) float g_attn[BB*LL*DD];
__device__ __align__(16) float g_h1[BB*CC*HM];
__device__ __align__(16) float g_qkv[BB*LL*3*DD];
__device__ __align__(16) float g_ao[BB*LL*DD];
__device__ __align__(16) float g_y[BB*LL*DD];
__device__ __align__(16) float g_kv[BB*LL*2*DD];
__device__ __align__(16) float g_z[BB*LL*HM];
__device__ __align__(16) float g_s[BB*LL*HM];
__device__ __align__(16) float g_dz[BB*LL*HM];
__device__ __align__(16) float g_e[BB*LL*DD];
__device__ float g_coef[BB*3];

// ---------------- init: fast weights, momentum, Wkv concat, persistent -----
__global__ void k_init(const float* __restrict__ mW1, const float* __restrict__ mb1,
                       const float* __restrict__ mW2, const float* __restrict__ mb2,
                       const float* __restrict__ pers,
                       const float* __restrict__ W_K, const float* __restrict__ W_V) {
    long i = (long)blockIdx.x * blockDim.x + threadIdx.x;
    if (i < (long)BB*DD*HM) {
        g_fastW1[i] = mW1[i % (DD*HM)]; g_momW1[i] = 0.f;
        g_fastW2[i] = mW2[i % (HM*DD)]; g_momW2[i] = 0.f;
    }
    if (i < BB*HM) { g_fastb1[i] = mb1[i % HM]; g_momb1[i] = 0.f; }
    if (i < BB*DD) { g_fastb2[i] = mb2[i % DD]; g_momb2[i] = 0.f; }
    if (i < DD*2*DD) {
        int k = (int)(i >> 9), n = (int)(i & 511);
        g_Wkv[i] = (n < DD) ? W_K[k*DD + n] : W_V[k*DD + n - DD];
    }
    if (i < BB*PP*DD) {
        int d = (int)(i % DD); int t = (int)((i/DD) % PP); int b = (int)(i/(PP*DD));
        g_attn[((long)b*LL + t)*DD + d] = pers[t*DD + d];
    }
}

// ---------------- pack the x slice into attn_in rows [PP+CC, LL) -----------
__global__ void k_packx(const float* __restrict__ x, int s0) {
    int i = blockIdx.x * blockDim.x + threadIdx.x;
    if (i >= BB*CC*DD) return;
    int d = i % DD, t = (i/DD) % CC, b = i/(CC*DD);
    g_attn[((long)b*LL + PP + CC + t)*DD + d] = x[(size_t)b*SS*DD + (size_t)(s0+t)*DD + d];
}

// ---------------- batched GEMM, 32x64 tile, 128 thr, double-buffered -------
// C[m,n] = (sum_k A[m,k] * B) + bias (+ epilogue)
// TB: B is N x K (C = A @ B^T), else K x N.
// EPI: 0 none, 1 silu, 2 store z->C and silu(z)->C2, 3 (acc+bias - X1)*LD_INV,
//      4 acc * silu'(X1) (no bias), 5 (acc+bias) * X1 (gate)
template<bool TB, bool BIAS, int EPI>
__global__ void k_bgemm(const float* __restrict__ A, const float* __restrict__ Bw,
                        const float* __restrict__ bias, float* __restrict__ C,
                        const float* __restrict__ X1, float* __restrict__ C2,
                        int M, int N, int K, int lda, int ldb, int ldc,
                        long sA, long sB, long sC, int sBias, long sX1, int ldx1) {
    __shared__ float As[2][16][36];
    __shared__ float Bs[2][16][68];
    int b = blockIdx.z;
    A  += (long)b * sA;
    Bw += (long)b * sB;
    C  += (long)b * sC;
    if (BIAS) bias += (long)b * sBias;
    if (EPI == 3 || EPI == 4 || EPI == 5) X1 += (long)b * sX1;
    if (EPI == 2) C2 += (long)b * sC;
    int tid = threadIdx.x;
    int n0 = blockIdx.x * 64;
    int m0 = blockIdx.y * 32;
    int tx = tid & 15, ty = tid >> 4;
    float acc[4][4] = {};
    int ar = tid >> 2;
    int ac = (tid & 3) * 4;
    int arow = m0 + ar; if (arow >= M) arow = M - 1;
    const float* Aptr = A + (long)arow*lda + ac;
    int nr = tid >> 2, kc = (tid & 3) * 4;   // TB
    int br = tid >> 4, bc = (tid & 15) * 4;  // !TB
    int nt = K / 16;
    float4 a4, b4a, b4b;
    a4 = *(const float4*)(Aptr);
    if (TB) {
        b4a = *(const float4*)(Bw + (long)(n0+nr)*ldb + kc);
        b4b = *(const float4*)(Bw + (long)(n0+nr+32)*ldb + kc);
    } else {
        b4a = *(const float4*)(Bw + (long)br*ldb + n0 + bc);
        b4b = *(const float4*)(Bw + (long)(br+8)*ldb + n0 + bc);
    }
    As[0][ac+0][ar]=a4.x; As[0][ac+1][ar]=a4.y; As[0][ac+2][ar]=a4.z; As[0][ac+3][ar]=a4.w;
    if (TB) {
        Bs[0][kc+0][nr]=b4a.x; Bs[0][kc+1][nr]=b4a.y; Bs[0][kc+2][nr]=b4a.z; Bs[0][kc+3][nr]=b4a.w;
        Bs[0][kc+0][nr+32]=b4b.x; Bs[0][kc+1][nr+32]=b4b.y; Bs[0][kc+2][nr+32]=b4b.z; Bs[0][kc+3][nr+32]=b4b.w;
    } else {
        *(float4*)&Bs[0][br][bc]   = b4a;
        *(float4*)&Bs[0][br+8][bc] = b4b;
    }
    __syncthreads();
    for (int kt = 0; kt < nt; kt++) {
        int cur = kt & 1;
        if (kt + 1 < nt) {
            int k1 = (kt + 1) * 16;
            a4 = *(const float4*)(Aptr + k1);
            if (TB) {
                b4a = *(const float4*)(Bw + (long)(n0+nr)*ldb + k1 + kc);
                b4b = *(const float4*)(Bw + (long)(n0+nr+32)*ldb + k1 + kc);
            } else {
                b4a = *(const float4*)(Bw + (long)(k1+br)*ldb + n0 + bc);
                b4b = *(const float4*)(Bw + (long)(k1+br+8)*ldb + n0 + bc);
            }
        }
        #pragma unroll
        for (int kk = 0; kk < 16; kk++) {
            float4 av = *(const float4*)&As[cur][kk][ty*4];
            float4 bv = *(const float4*)&Bs[cur][kk][tx*4];
            float a[4] = {av.x, av.y, av.z, av.w};
            float bb2[4] = {bv.x, bv.y, bv.z, bv.w};
            #pragma unroll
            for (int i = 0; i < 4; i++)
                #pragma unroll
                for (int j = 0; j < 4; j++) acc[i][j] += a[i] * bb2[j];
        }
        if (kt + 1 < nt) {
            int nxt = cur ^ 1;
            As[nxt][ac+0][ar]=a4.x; As[nxt][ac+1][ar]=a4.y; As[nxt][ac+2][ar]=a4.z; As[nxt][ac+3][ar]=a4.w;
            if (TB) {
                Bs[nxt][kc+0][nr]=b4a.x; Bs[nxt][kc+1][nr]=b4a.y; Bs[nxt][kc+2][nr]=b4a.z; Bs[nxt][kc+3][nr]=b4a.w;
                Bs[nxt][kc+0][nr+32]=b4b.x; Bs[nxt][kc+1][nr+32]=b4b.y; Bs[nxt][kc+2][nr+32]=b4b.z; Bs[nxt][kc+3][nr+32]=b4b.w;
            } else {
                *(float4*)&Bs[nxt][br][bc]   = b4a;
                *(float4*)&Bs[nxt][br+8][bc] = b4b;
            }
        }
        __syncthreads();
    }
    #pragma unroll
    for (int i = 0; i < 4; i++) {
        int row = m0 + ty*4 + i;
        if (row < M) {
            #pragma unroll
            for (int j = 0; j < 4; j++) {
                int col = n0 + tx*4 + j;
                float v = acc[i][j];
                if (BIAS) v += bias[col];
                if (EPI == 1) v = v / (1.f + expf(-v));
                else if (EPI == 2) C2[(long)row*ldc + col] = v / (1.f + expf(-v));
                else if (EPI == 3) v = (v - X1[(long)row*ldx1 + col]) * LD_INV;
                else if (EPI == 4) {
                    float z = X1[(long)row*ldx1 + col];
                    float sig = 1.f / (1.f + expf(-z));
                    v = v * sig * (1.f + z * (1.f - sig));
                }
                else if (EPI == 5) v = v * X1[(long)row*ldx1 + col];
                C[(long)row*ldc + col] = v;
            }
        }
    }
}

// ---------------- batched transpose-A GEMM: C[m,n] = sum_t A[t,m]*B[t,n] ---
// Also emits column sums of B (bias gradients) from blocks with blockIdx.y==0.
__global__ void k_gemmTA(const float* __restrict__ A, const float* __restrict__ B,
                         float* __restrict__ C, float* __restrict__ gb,
                         int T, int M, int N, int lda, int ldb, int ldc,
                         long sA, long sB, long sC, int sGB) {
    __shared__ float As[2][8][36];
    __shared__ float Bs[2][8][68];
    int b = blockIdx.z;
    A += (long)b*sA; B += (long)b*sB; C += (long)b*sC;
    int tid = threadIdx.x;
    int n0 = blockIdx.x * 64, m0 = blockIdx.y * 32;
    int tx = tid & 15, ty = tid >> 4;
    float acc[4][4] = {};
    float bsum[4] = {};
    int lr = tid >> 4;            // 0..7
    int lca = (tid & 15) * 2;     // A cols
    int lcb = (tid & 15) * 4;     // B cols
    int nt = T / 8;
    float2 a2 = *(const float2*)(A + (long)lr*lda + m0 + lca);
    float4 b4 = *(const float4*)(B + (long)lr*ldb + n0 + lcb);
    *(float2*)&As[0][lr][lca] = a2;
    *(float4*)&Bs[0][lr][lcb] = b4;
    __syncthreads();
    for (int kt = 0; kt < nt; kt++) {
        int cur = kt & 1;
        if (kt + 1 < nt) {
            int t1 = (kt+1)*8 + lr;
            a2 = *(const float2*)(A + (long)t1*lda + m0 + lca);
            b4 = *(const float4*)(B + (long)t1*ldb + n0 + lcb);
        }
        #pragma unroll
        for (int kk = 0; kk < 8; kk++) {
            float4 av = *(const float4*)&As[cur][kk][ty*4];
            float4 bv = *(const float4*)&Bs[cur][kk][tx*4];
            float a[4] = {av.x, av.y, av.z, av.w};
            float bb2[4] = {bv.x, bv.y, bv.z, bv.w};
            #pragma unroll
            for (int i = 0; i < 4; i++)
                #pragma unroll
                for (int j = 0; j < 4; j++) acc[i][j] += a[i] * bb2[j];
            if (ty == 0) { bsum[0]+=bb2[0]; bsum[1]+=bb2[1]; bsum[2]+=bb2[2]; bsum[3]+=bb2[3]; }
        }
        if (kt + 1 < nt) {
            int nxt = cur ^ 1;
            *(float2*)&As[nxt][lr][lca] = a2;
            *(float4*)&Bs[nxt][lr][lcb] = b4;
        }
        __syncthreads();
    }
    #pragma unroll
    for (int i = 0; i < 4; i++)
        #pragma unroll
        for (int j = 0; j < 4; j++)
            C[(long)(m0+ty*4+i)*ldc + n0+tx*4+j] = acc[i][j];
    if (ty == 0 && blockIdx.y == 0) {
        gb += (long)b * sGB;
        #pragma unroll
        for (int j = 0; j < 4; j++) gb[n0 + tx*4 + j] = bsum[j];
    }
}

// ---------------- attention: block = (b, head, 8-row tile), smem K/V -------
__global__ void k_attn2() {
    __shared__ float Ks[64][33];
    __shared__ float Vs[64][33];
    __shared__ float qs[8][32];
    __shared__ float ps[8][32];
    int blk = blockIdx.x;
    int tile = blk % (LL/8);
    int hh = (blk / (LL/8)) % NH;
    int b  = blk / ((LL/8)*NH);
    int rt0 = tile * 8;
    int tid = threadIdx.x;
    int w = tid >> 5, lane = tid & 31;
    int r = rt0 + w;
    const float* base = g_qkv + (long)b*LL*3*DD;
    qs[w][lane] = base[(long)r*3*DD + hh*HD + lane] * 0.17677669529663687f;
    float m = -1e30f, l = 0.f, o = 0.f;
    int ntile = (rt0 + 71) >> 6;
    int krow = tid >> 3;          // 0..31
    int kc = (tid & 7) * 4;       // 0..28
    for (int jt = 0; jt < ntile; jt++) {
        int j0 = jt * 64;
        __syncthreads();
        #pragma unroll
        for (int half = 0; half < 2; half++) {
            int jl = krow + half*32;
            int jg = j0 + jl; if (jg > LL-1) jg = LL-1;
            const float* kp = base + (long)jg*3*DD + DD + hh*HD + kc;
            float4 k4 = *(const float4*)kp;
            float4 v4 = *(const float4*)(kp + DD);
            Ks[jl][kc]=k4.x; Ks[jl][kc+1]=k4.y; Ks[jl][kc+2]=k4.z; Ks[jl][kc+3]=k4.w;
            Vs[jl][kc]=v4.x; Vs[jl][kc+1]=v4.y; Vs[jl][kc+2]=v4.z; Vs[jl][kc+3]=v4.w;
        }
        __syncthreads();
        #pragma unroll
        for (int c = 0; c < 2; c++) {
            int jbase = j0 + c*32;
            if (jbase > r) break;
            int jl = c*32 + lane;
            int jg = jbase + lane;
            float sc = 0.f;
            #pragma unroll
            for (int d = 0; d < 32; d++) sc += qs[w][d] * Ks[jl][d];
            if (jg > r) sc = -1e30f;
            float cm = sc;
            #pragma unroll
            for (int s = 16; s; s >>= 1) cm = fmaxf(cm, __shfl_xor_sync(0xffffffffu, cm, s));
            float mn = fmaxf(m, cm);
            float p = (jg <= r) ? expf(sc - mn) : 0.f;
            __syncwarp();
            ps[w][lane] = p;
            float psum = p;
            #pragma unroll
            for (int s = 16; s; s >>= 1) psum += __shfl_xor_sync(0xffffffffu, psum, s);
            float corr = expf(m - mn);
            l = l*corr + psum; o *= corr; m = mn;
            __syncwarp();
            int jmax = min(32, r - jbase + 1);
            for (int jj = 0; jj < jmax; jj++)
                o += ps[w][jj] * Vs[c*32 + jj][lane];
        }
    }
    g_ao[((long)b*LL + r)*DD + hh*HD + lane] = o / l;
}

// ---------------- gate coefficients ----------------------------------------
__global__ void k_coef(const float* __restrict__ cW1, const float* __restrict__ cb1,
                       const float* __restrict__ cW2, const float* __restrict__ cb2) {
    int b = blockIdx.x, tid = threadIdx.x;
    __shared__ float ybar[DD];
    __shared__ float ch[CHN];
    float sum = 0.f;
    const float* yp = g_y + (long)b*LL*DD + tid;
    for (int t = 0; t < LL; t++) sum += yp[(long)t*DD];
    ybar[tid] = sum / (float)LL;
    __syncthreads();
    if (tid < CHN) {
        float a = cb1[tid];
        for (int d = 0; d < DD; d++) a += ybar[d] * cW1[d*CHN + tid];
        ch[tid] = a / (1.f + expf(-a));
    }
    __syncthreads();
    if (tid < 3) {
        float a = cb2[tid];
        for (int j = 0; j < CHN; j++) a += ch[j] * cW2[j*3 + tid];
        g_coef[b*3 + tid] = 1.f / (1.f + expf(-a));
    }
}

// ---------------- momentum + decay update ----------------------------------
__global__ void k_update() {
    long i = (long)blockIdx.x * blockDim.x + threadIdx.x;
    if (i >= (long)BB*PER) return;
    int b = (int)(i / PER), off = (int)(i % PER);
    float alpha = g_coef[b*3+0], eta = g_coef[b*3+1], theta = g_coef[b*3+2];
    float *fp, *mp, *gp;
    long idx;
    if (off < DD*HM)                   { fp = g_fastW1; mp = g_momW1; gp = g_gW1; idx = (long)b*DD*HM + off; }
    else if (off < DD*HM + HM)         { int o = off - DD*HM; fp = g_fastb1; mp = g_momb1; gp = g_gb1; idx = b*HM + o; }
    else if (off < DD*HM + HM + HM*DD) { int o = off - DD*HM - HM; fp = g_fastW2; mp = g_momW2; gp = g_gW2; idx = (long)b*HM*DD + o; }
    else                               { int o = off - DD*HM - HM - HM*DD; fp = g_fastb2; mp = g_momb2; gp = g_gb2; idx = b*DD + o; }
    float m = eta * mp[idx] - theta * gp[idx];
    mp[idx] = m;
    fp[idx] = (1.f - alpha) * fp[idx] + m;
}

// ---------------------------------------------------------------------------
extern "C" void kernel_launch(void* const* d_in, const int* in_sizes, int n_in,
                              void* d_out, int out_size) {
    const float* x     = (const float*)d_in[0];
    const float* pers  = (const float*)d_in[1];
    const float* W_Q   = (const float*)d_in[2];
    const float* in_w  = (const float*)d_in[3];
    const float* in_b  = (const float*)d_in[4];
    const float* out_w = (const float*)d_in[5];
    const float* out_b = (const float*)d_in[6];
    const float* mW1   = (const float*)d_in[7];
    const float* mb1   = (const float*)d_in[8];
    const float* mW2   = (const float*)d_in[9];
    const float* mb2   = (const float*)d_in[10];
    const float* W_K   = (const float*)d_in[11];
    const float* W_V   = (const float*)d_in[12];
    const float* cW1   = (const float*)d_in[13];
    const float* cb1   = (const float*)d_in[14];
    const float* cW2   = (const float*)d_in[15];
    const float* cb2   = (const float*)d_in[16];
    float* out = (float*)d_out;

    float *fW1, *fb1, *fW2, *fb2, *pQall, *pWkv, *pAttn, *pH1, *pQkv, *pAo, *pY;
    float *pKV, *pZ, *pS, *pDz, *pE, *pGW1, *pGW2, *pGb1, *pGb2;
    cudaGetSymbolAddress((void**)&fW1, g_fastW1);
    cudaGetSymbolAddress((void**)&fb1, g_fastb1);
    cudaGetSymbolAddress((void**)&fW2, g_fastW2);
    cudaGetSymbolAddress((void**)&fb2, g_fastb2);
    cudaGetSymbolAddress((void**)&pQall, g_qall);
    cudaGetSymbolAddress((void**)&pWkv, g_Wkv);
    cudaGetSymbolAddress((void**)&pAttn, g_attn);
    cudaGetSymbolAddress((void**)&pH1, g_h1);
    cudaGetSymbolAddress((void**)&pQkv, g_qkv);
    cudaGetSymbolAddress((void**)&pAo, g_ao);
    cudaGetSymbolAddress((void**)&pY, g_y);
    cudaGetSymbolAddress((void**)&pKV, g_kv);
    cudaGetSymbolAddress((void**)&pZ, g_z);
    cudaGetSymbolAddress((void**)&pS, g_s);
    cudaGetSymbolAddress((void**)&pDz, g_dz);
    cudaGetSymbolAddress((void**)&pE, g_e);
    cudaGetSymbolAddress((void**)&pGW1, g_gW1);
    cudaGetSymbolAddress((void**)&pGW2, g_gW2);
    cudaGetSymbolAddress((void**)&pGb1, g_gb1);
    cudaGetSymbolAddress((void**)&pGb2, g_gb2);

    k_init<<<((long)BB*DD*HM + 255)/256, 256>>>(mW1, mb1, mW2, mb2, pers, W_K, W_V);

    // q for ALL segments up front: Q_all = x @ W_Q  (M = 32768)
    k_bgemm<false,false,0><<<dim3(DD/64, (BB*SS)/32, 1), 128>>>(
        x, W_Q, nullptr, pQall, nullptr, nullptr,
        BB*SS, DD, DD, DD, DD, DD, 0L, 0L, 0L, 0, 0L, 0);

    for (int s = 0; s < NSEG; s++) {
        int s0 = s * CC;
        k_packx<<<(BB*CC*DD + 255)/256, 256>>>(x, s0);

        // h1 = silu(q_seg @ fastW1 + fastb1)
        k_bgemm<false,true,1><<<dim3(HM/64, CC/32, BB), 128>>>(
            pQall + (long)s0*DD, fW1, fb1, pH1, nullptr, nullptr,
            CC, HM, DD, DD, HM, HM, (long)SS*DD, (long)DD*HM, (long)CC*HM, HM, 0L, 0);
        // h = h1 @ fastW2 + fastb2 -> attn_in rows [PP, PP+CC)
        k_bgemm<false,true,0><<<dim3(DD/64, CC/32, BB), 128>>>(
            pH1, fW2, fb2, pAttn + PP*DD, nullptr, nullptr,
            CC, DD, HM, HM, DD, DD, (long)CC*HM, (long)HM*DD, (long)LL*DD, DD, 0L, 0);

        // qkv = attn_in @ in_proj_w^T + in_proj_b   (M = 4224 contiguous)
        k_bgemm<true,true,0><<<dim3((3*DD)/64, (BB*LL)/32, 1), 128>>>(
            pAttn, in_w, in_b, pQkv, nullptr, nullptr,
            BB*LL, 3*DD, DD, DD, DD, 3*DD, 0L, 0L, 0L, 0, 0L, 0);
        k_attn2<<<BB*NH*(LL/8), 256>>>();
        // y = ao @ out_proj_w^T + out_proj_b
        k_bgemm<true,true,0><<<dim3(DD/64, (BB*LL)/32, 1), 128>>>(
            pAo, out_w, out_b, pY, nullptr, nullptr,
            BB*LL, DD, DD, DD, DD, DD, 0L, 0L, 0L, 0, 0L, 0);
        // [k|v] = y @ Wkv
        k_bgemm<false,false,0><<<dim3((2*DD)/64, (BB*LL)/32, 1), 128>>>(
            pY, pWkv, nullptr, pKV, nullptr, nullptr,
            BB*LL, 2*DD, DD, DD, 2*DD, 2*DD, 0L, 0L, 0L, 0, 0L, 0);

        // z = k @ W1 + b1 ; s = silu(z)
        k_bgemm<false,true,2><<<dim3(HM/64, (LL+31)/32, BB), 128>>>(
            pKV, fW1, fb1, pZ, nullptr, pS,
            LL, HM, DD, 2*DD, HM, HM, (long)LL*2*DD, (long)DD*HM, (long)LL*HM, HM, 0L, 0);
        // e = (s @ W2 + b2 - v) * LD_INV
        k_bgemm<false,true,3><<<dim3(DD/64, (LL+31)/32, BB), 128>>>(
            pS, fW2, fb2, pE, pKV + DD, nullptr,
            LL, DD, HM, HM, DD, DD, (long)LL*HM, (long)HM*DD, (long)LL*DD, DD, (long)LL*2*DD, 2*DD);
        // dz = (e @ W2^T) * silu'(z)
        k_bgemm<true,false,4><<<dim3(HM/64, (LL+31)/32, BB), 128>>>(
            pE, fW2, nullptr, pDz, pZ, nullptr,
            LL, HM, DD, DD, DD, HM, (long)LL*DD, (long)HM*DD, (long)LL*HM, 0, (long)LL*HM, HM);
        // gW2[h,d] = sum_t s[t,h] e[t,d] ; gb2 = colsum(e)
        k_gemmTA<<<dim3(DD/64, HM/32, BB), 128>>>(
            pS, pE, pGW2, pGb2, LL, HM, DD, HM, DD, DD,
            (long)LL*HM, (long)LL*DD, (long)HM*DD, DD);
        // gW1[d,h] = sum_t k[t,d] dz[t,h] ; gb1 = colsum(dz)
        k_gemmTA<<<dim3(HM/64, DD/32, BB), 128>>>(
            pKV, pDz, pGW1, pGb1, LL, DD, HM, 2*DD, HM, HM,
            (long)LL*2*DD, (long)LL*HM, (long)DD*HM, HM);

        k_coef<<<BB, 256>>>(cW1, cb1, cW2, cb2);
        k_update<<<((long)BB*PER + 255)/256, 256>>>();

        // final: mem_apply(updated weights, y_last) gated by y_last -> out
        k_bgemm<false,true,1><<<dim3(HM/64, CC/32, BB), 128>>>(
            pY + (long)(PP+CC)*DD, fW1, fb1, pH1, nullptr, nullptr,
            CC, HM, DD, DD, HM, HM, (long)LL*DD, (long)DD*HM, (long)CC*HM, HM, 0L, 0);
        k_bgemm<false,true,5><<<dim3(DD/64, CC/32, BB), 128>>>(
            pH1, fW2, fb2, out + (long)s0*DD, pY + (long)(PP+CC)*DD, nullptr,
            CC, DD, HM, HM, DD, DD, (long)CC*HM, (long)HM*DD, (long)SS*DD, DD, (long)LL*DD, DD);
    }
}